// round 13
// baseline (speedup 1.0000x reference)
#include <cuda_runtime.h>
#include <cuda_fp16.h>
#include <cstdint>

#define NMAX 100000
#define EMAX 1600000
#define DD 128
#define SCB 1024   // scan tile size

// ---- scratch (device globals: allocation-free rule) ----
__device__ int    g_deg[NMAX];
__device__ float  g_dinv[NMAX];
__device__ int    g_rowptr[NMAX + 1];
__device__ int    g_cursor[NMAX];
__device__ __align__(16) int2 g_colw[EMAX];
__device__ int    g_bsum[(NMAX + SCB - 1) / SCB];
__device__ int    g_boff[(NMAX + SCB - 1) / SCB];
__device__ __half g_H[(size_t)NMAX * DD];
__device__ __half g_T[(size_t)NMAX * DD];
__device__ __align__(16) __half g_W16[2 * DD * DD];

// ---------------- preprocessing (R10 form — frozen) ----------------
__global__ void k_count(const int* __restrict__ row, int E) {
    int i = blockIdx.x * blockDim.x + threadIdx.x;
    if (i < E) atomicAdd(&g_deg[row[i]], 1);
}

__global__ void __launch_bounds__(SCB) k_blocksum_dinv(int n) {
    __shared__ int s[SCB];
    int i = blockIdx.x * SCB + threadIdx.x;
    int d = 0;
    if (i < n) {
        d = g_deg[i];
        g_dinv[i] = rsqrtf((float)(d + 1));  // +1 self loop
    }
    s[threadIdx.x] = d;
    __syncthreads();
#pragma unroll
    for (int off = SCB / 2; off > 0; off >>= 1) {
        if (threadIdx.x < off) s[threadIdx.x] += s[threadIdx.x + off];
        __syncthreads();
    }
    if (threadIdx.x == 0) g_bsum[blockIdx.x] = s[0];
}

__global__ void k_bscan(int nb) {
    __shared__ int s[128];
    int t = threadIdx.x;
    s[t] = (t < nb) ? g_bsum[t] : 0;
    __syncthreads();
#pragma unroll
    for (int off = 1; off < 128; off <<= 1) {
        int v = (t >= off) ? s[t - off] : 0;
        __syncthreads();
        s[t] += v;
        __syncthreads();
    }
    if (t < nb) g_boff[t] = (t == 0) ? 0 : s[t - 1];
}

__global__ void __launch_bounds__(SCB) k_blockscan(int n) {
    __shared__ int s[SCB];
    int i = blockIdx.x * SCB + threadIdx.x;
    int d = (i < n) ? g_deg[i] : 0;
    s[threadIdx.x] = d;
    __syncthreads();
#pragma unroll
    for (int off = 1; off < SCB; off <<= 1) {
        int v = (threadIdx.x >= off) ? s[threadIdx.x - off] : 0;
        __syncthreads();
        s[threadIdx.x] += v;
        __syncthreads();
    }
    int boff = g_boff[blockIdx.x];
    if (i < n) {
        int excl = boff + s[threadIdx.x] - d;
        g_rowptr[i] = excl;
        g_cursor[i] = excl;
        if (i == n - 1) g_rowptr[n] = boff + s[threadIdx.x];
    }
}

__global__ void k_scatter(const int* __restrict__ row, const int* __restrict__ col, int E) {
    int i = blockIdx.x * blockDim.x + threadIdx.x;
    if (i < E) {
        int r = row[i];
        int c = col[i];
        int p = atomicAdd(&g_cursor[r], 1);
        float w = g_dinv[r] * g_dinv[c];
        g_colw[p] = make_int2(c, __float_as_int(w));
    }
}

__global__ void k_convW(const float* __restrict__ Wa, const float* __restrict__ Wb) {
    int i = blockIdx.x * blockDim.x + threadIdx.x;
    if (i < 4096) {
        float4 v = ((const float4*)Wa)[i];
        half2 lo = __floats2half2_rn(v.x, v.y);
        half2 hi = __floats2half2_rn(v.z, v.w);
        uint2 pk;
        pk.x = *(unsigned int*)&lo;
        pk.y = *(unsigned int*)&hi;
        ((uint2*)g_W16)[i] = pk;
        v = ((const float4*)Wb)[i];
        lo = __floats2half2_rn(v.x, v.y);
        hi = __floats2half2_rn(v.z, v.w);
        pk.x = *(unsigned int*)&lo;
        pk.y = *(unsigned int*)&hi;
        ((uint2*)g_W16)[4096 + i] = pk;
    }
}

// ---------------- shared gather (edge loop) ----------------
__device__ __forceinline__ float4 gather_row(const uint2* __restrict__ H2,
                                             int gw, unsigned lane) {
    float di = g_dinv[gw];
    float ws = di * di;   // self-loop weight

    uint2 hp = __ldg(&H2[((unsigned)gw << 5) + lane]);
    float2 h01 = __half22float2(*(half2*)&hp.x);
    float2 h23 = __half22float2(*(half2*)&hp.y);
    float4 acc;
    acc.x = ws * h01.x; acc.y = ws * h01.y; acc.z = ws * h23.x; acc.w = ws * h23.y;

    int s = g_rowptr[gw];
    int e = g_rowptr[gw + 1];
    int j = s;

#define EDGE_FMA_V(V, WB)                                                      \
    do {                                                                       \
        float w_ = __int_as_float(WB);                                         \
        float2 a_ = __half22float2(*(half2*)&(V).x);                           \
        float2 b_ = __half22float2(*(half2*)&(V).y);                           \
        acc.x = fmaf(w_, a_.x, acc.x);                                         \
        acc.y = fmaf(w_, a_.y, acc.y);                                         \
        acc.z = fmaf(w_, b_.x, acc.z);                                         \
        acc.w = fmaf(w_, b_.y, acc.w);                                         \
    } while (0)

    if (j < e && (j & 1)) {
        int2 cw = __ldg(&g_colw[j]);
        uint2 v = __ldg(&H2[((unsigned)cw.x << 5) + lane]);
        EDGE_FMA_V(v, cw.y);
        j++;
    }
    for (; j + 7 < e; j += 8) {
        int4 q0 = __ldg((const int4*)&g_colw[j]);
        int4 q1 = __ldg((const int4*)&g_colw[j + 2]);
        int4 q2 = __ldg((const int4*)&g_colw[j + 4]);
        int4 q3 = __ldg((const int4*)&g_colw[j + 6]);
        uint2 v0 = __ldg(&H2[((unsigned)q0.x << 5) + lane]);
        uint2 v1 = __ldg(&H2[((unsigned)q0.z << 5) + lane]);
        uint2 v2 = __ldg(&H2[((unsigned)q1.x << 5) + lane]);
        uint2 v3 = __ldg(&H2[((unsigned)q1.z << 5) + lane]);
        uint2 v4 = __ldg(&H2[((unsigned)q2.x << 5) + lane]);
        uint2 v5 = __ldg(&H2[((unsigned)q2.z << 5) + lane]);
        uint2 v6 = __ldg(&H2[((unsigned)q3.x << 5) + lane]);
        uint2 v7 = __ldg(&H2[((unsigned)q3.z << 5) + lane]);
        EDGE_FMA_V(v0, q0.y);
        EDGE_FMA_V(v1, q0.w);
        EDGE_FMA_V(v2, q1.y);
        EDGE_FMA_V(v3, q1.w);
        EDGE_FMA_V(v4, q2.y);
        EDGE_FMA_V(v5, q2.w);
        EDGE_FMA_V(v6, q3.y);
        EDGE_FMA_V(v7, q3.w);
    }
    for (; j + 1 < e; j += 2) {
        int4 q = __ldg((const int4*)&g_colw[j]);
        uint2 v0 = __ldg(&H2[((unsigned)q.x << 5) + lane]);
        uint2 v1 = __ldg(&H2[((unsigned)q.z << 5) + lane]);
        EDGE_FMA_V(v0, q.y);
        EDGE_FMA_V(v1, q.w);
    }
    if (j < e) {
        int2 cw = __ldg(&g_colw[j]);
        uint2 v = __ldg(&H2[((unsigned)cw.x << 5) + lane]);
        EDGE_FMA_V(v, cw.y);
    }
#undef EDGE_FMA_V
    return acc;
}

// ---------------- tensor-core helpers ----------------
__device__ __forceinline__ void ldsm4(uint32_t (&r)[4], const void* p) {
    uint32_t a = (uint32_t)__cvta_generic_to_shared(p);
    asm volatile("ldmatrix.sync.aligned.m8n8.x4.shared.b16 {%0,%1,%2,%3}, [%4];"
                 : "=r"(r[0]), "=r"(r[1]), "=r"(r[2]), "=r"(r[3]) : "r"(a));
}
__device__ __forceinline__ void ldsm4t(uint32_t (&r)[4], const void* p) {
    uint32_t a = (uint32_t)__cvta_generic_to_shared(p);
    asm volatile("ldmatrix.sync.aligned.m8n8.x4.trans.shared.b16 {%0,%1,%2,%3}, [%4];"
                 : "=r"(r[0]), "=r"(r[1]), "=r"(r[2]), "=r"(r[3]) : "r"(a));
}
__device__ __forceinline__ void mma16816(float (&c)[4], const uint32_t (&a)[4],
                                         uint32_t b0, uint32_t b1) {
    asm volatile(
        "mma.sync.aligned.m16n8k16.row.col.f32.f16.f16.f32 "
        "{%0,%1,%2,%3}, {%4,%5,%6,%7}, {%8,%9}, {%0,%1,%2,%3};"
        : "+f"(c[0]), "+f"(c[1]), "+f"(c[2]), "+f"(c[3])
        : "r"(a[0]), "r"(a[1]), "r"(a[2]), "r"(a[3]), "r"(b0), "r"(b1));
}

#define ASTRIDE 136
#define GEMM_SMEM ((2 * 64 + 128) * ASTRIDE * 2)   // persistent gemm1
#define FUSED_SMEM ((64 + 128) * ASTRIDE * 2)       // fused aggr+gemm

// ---------------- persistent tensor-core GEMM (layer 1, fp32 in/W) ----------------
__global__ void __launch_bounds__(256) k_gemm_ps(const float* __restrict__ Xv,
                                                 const float* __restrict__ Wv,
                                                 __half* __restrict__ H, int n) {
    extern __shared__ __half sm[];
    __half* As2 = sm;                       // 2 x [64][ASTRIDE]
    __half* Bs = sm + 2 * 64 * ASTRIDE;     // [128][ASTRIDE]
    int t = threadIdx.x;

    const float4* W4 = (const float4*)Wv;
    for (int i = t; i < 4096; i += 256) {
        int r = i >> 5, c = (i & 31) * 4;
        float4 v = W4[i];
        *(half2*)&Bs[r * ASTRIDE + c]     = __floats2half2_rn(v.x, v.y);
        *(half2*)&Bs[r * ASTRIDE + c + 2] = __floats2half2_rn(v.z, v.w);
    }

    int lane = t & 31;
    int wid = t >> 5;
    int wm = (wid & 3) * 16;
    int wn = (wid >> 2) * 64;
    int lr = lane & 15;
    int lc = (lane >> 4) * 8;

    int buf = 0;
    for (int row0 = blockIdx.x * 64; row0 < n; row0 += gridDim.x * 64, buf ^= 1) {
        __half* As = As2 + buf * 64 * ASTRIDE;
        const float4* X4 = (const float4*)Xv;
        for (int i = t; i < 2048; i += 256) {
            int r = i >> 5, c = (i & 31) * 4;
            float4 v = (row0 + r < n) ? X4[(size_t)(row0 + r) * 32 + (i & 31)]
                                      : make_float4(0.f, 0.f, 0.f, 0.f);
            *(half2*)&As[r * ASTRIDE + c]     = __floats2half2_rn(v.x, v.y);
            *(half2*)&As[r * ASTRIDE + c + 2] = __floats2half2_rn(v.z, v.w);
        }
        __syncthreads();

        float acc[8][4];
#pragma unroll
        for (int i = 0; i < 8; i++) { acc[i][0] = 0.f; acc[i][1] = 0.f; acc[i][2] = 0.f; acc[i][3] = 0.f; }

#pragma unroll
        for (int k0 = 0; k0 < 128; k0 += 16) {
            uint32_t a[4];
            ldsm4(a, &As[(wm + lr) * ASTRIDE + k0 + lc]);
#pragma unroll
            for (int p = 0; p < 4; p++) {
                uint32_t b[4];
                ldsm4t(b, &Bs[(k0 + lr) * ASTRIDE + wn + p * 16 + lc]);
                mma16816(acc[2 * p],     a, b[0], b[1]);
                mma16816(acc[2 * p + 1], a, b[2], b[3]);
            }
        }

        int orow = row0 + wm + (lane >> 2);
#pragma unroll
        for (int nt = 0; nt < 8; nt++) {
            int ocol = wn + nt * 8 + (lane & 3) * 2;
            if (orow < n)
                *(half2*)&H[(size_t)orow * 128 + ocol] = __floats2half2_rn(acc[nt][0], acc[nt][1]);
            if (orow + 8 < n)
                *(half2*)&H[(size_t)(orow + 8) * 128 + ocol] = __floats2half2_rn(acc[nt][2], acc[nt][3]);
        }
    }
}

// ---------------- FUSED: aggregate + bias + LN + ReLU + GEMM(W) ----------------
// One block per 64-node tile. Warp w aggregates nodes [tile + w*8, +8) into smem
// A-tile (LN output, fp16), then the block runs the HMMA tile GEMM A @ W -> Hout.
__global__ void __launch_bounds__(256) k_aggr_gemm(const __half* __restrict__ Hin,
                                                   const __half* __restrict__ W16,
                                                   __half* __restrict__ Hout,
                                                   const float* __restrict__ bias,
                                                   const float* __restrict__ gamma,
                                                   const float* __restrict__ beta,
                                                   int n) {
    extern __shared__ __half sm[];
    __half* As = sm;                    // [64][ASTRIDE]
    __half* Bs = sm + 64 * ASTRIDE;     // [128][ASTRIDE]
    int t = threadIdx.x;
    unsigned lane = t & 31;
    int wid = t >> 5;
    int row0 = blockIdx.x * 64;

    // load W (fp16) into Bs
    const uint2* W2 = (const uint2*)W16;
    for (int i = t; i < 4096; i += 256) {
        int r = i >> 5, c = (i & 31) * 4;
        *(uint2*)&Bs[r * ASTRIDE + c] = W2[i];
    }

    // aggregation phase: warp wid -> rows [wid*8, wid*8+8) of this tile
    const uint2* H2 = (const uint2*)Hin;
    float4 b = ((const float4*)bias)[lane];
    float4 g = ((const float4*)gamma)[lane];
    float4 be = ((const float4*)beta)[lane];

    for (int r = 0; r < 8; r++) {
        int arow = wid * 8 + r;
        int gw = row0 + arow;
        uint2 pk = make_uint2(0u, 0u);
        if (gw < n) {
            float4 acc = gather_row(H2, gw, lane);
            acc.x += b.x; acc.y += b.y; acc.z += b.z; acc.w += b.w;

            float sum = acc.x + acc.y + acc.z + acc.w;
            float sq = acc.x * acc.x + acc.y * acc.y + acc.z * acc.z + acc.w * acc.w;
#pragma unroll
            for (int o = 16; o > 0; o >>= 1) {
                sum += __shfl_xor_sync(0xffffffffu, sum, o);
                sq  += __shfl_xor_sync(0xffffffffu, sq, o);
            }
            float mu = sum * (1.0f / 128.0f);
            float var = sq * (1.0f / 128.0f) - mu * mu;
            float rstd = rsqrtf(var + 1e-5f);

            float ox = fmaxf(fmaf((acc.x - mu) * rstd, g.x, be.x), 0.f);
            float oy = fmaxf(fmaf((acc.y - mu) * rstd, g.y, be.y), 0.f);
            float oz = fmaxf(fmaf((acc.z - mu) * rstd, g.z, be.z), 0.f);
            float ow = fmaxf(fmaf((acc.w - mu) * rstd, g.w, be.w), 0.f);
            half2 lo = __floats2half2_rn(ox, oy);
            half2 hi = __floats2half2_rn(oz, ow);
            pk.x = *(unsigned int*)&lo;
            pk.y = *(unsigned int*)&hi;
        }
        *(uint2*)&As[arow * ASTRIDE + lane * 4] = pk;
    }
    __syncthreads();

    // GEMM phase: As[64x128] @ Bs[128x128] -> Hout rows [row0, row0+64)
    int wm = (wid & 3) * 16;
    int wn = (wid >> 2) * 64;
    int lr = (int)lane & 15;
    int lc = ((int)lane >> 4) * 8;

    float acc[8][4];
#pragma unroll
    for (int i = 0; i < 8; i++) { acc[i][0] = 0.f; acc[i][1] = 0.f; acc[i][2] = 0.f; acc[i][3] = 0.f; }

#pragma unroll
    for (int k0 = 0; k0 < 128; k0 += 16) {
        uint32_t a[4];
        ldsm4(a, &As[(wm + lr) * ASTRIDE + k0 + lc]);
#pragma unroll
        for (int p = 0; p < 4; p++) {
            uint32_t bb[4];
            ldsm4t(bb, &Bs[(k0 + lr) * ASTRIDE + wn + p * 16 + lc]);
            mma16816(acc[2 * p],     a, bb[0], bb[1]);
            mma16816(acc[2 * p + 1], a, bb[2], bb[3]);
        }
    }

    int orow = row0 + wm + ((int)lane >> 2);
#pragma unroll
    for (int nt = 0; nt < 8; nt++) {
        int ocol = wn + nt * 8 + ((int)lane & 3) * 2;
        if (orow < n)
            *(half2*)&Hout[(size_t)orow * 128 + ocol] = __floats2half2_rn(acc[nt][0], acc[nt][1]);
        if (orow + 8 < n)
            *(half2*)&Hout[(size_t)(orow + 8) * 128 + ocol] = __floats2half2_rn(acc[nt][2], acc[nt][3]);
    }
}

// ---------------- final aggregate + bias + LN + ReLU (fp32 out) ----------------
__global__ void __launch_bounds__(256) k_aggr_f32(const __half* __restrict__ H,
                                                  float* __restrict__ out,
                                                  const float* __restrict__ bias,
                                                  const float* __restrict__ gamma,
                                                  const float* __restrict__ beta,
                                                  int n) {
    int gw = (blockIdx.x * blockDim.x + threadIdx.x) >> 5;
    unsigned lane = threadIdx.x & 31;
    if (gw >= n) return;

    const uint2* H2 = (const uint2*)H;
    float4 acc = gather_row(H2, gw, lane);

    float4 b = ((const float4*)bias)[lane];
    acc.x += b.x; acc.y += b.y; acc.z += b.z; acc.w += b.w;

    float sum = acc.x + acc.y + acc.z + acc.w;
    float sq = acc.x * acc.x + acc.y * acc.y + acc.z * acc.z + acc.w * acc.w;
#pragma unroll
    for (int o = 16; o > 0; o >>= 1) {
        sum += __shfl_xor_sync(0xffffffffu, sum, o);
        sq  += __shfl_xor_sync(0xffffffffu, sq, o);
    }
    float mu = sum * (1.0f / 128.0f);
    float var = sq * (1.0f / 128.0f) - mu * mu;
    float rstd = rsqrtf(var + 1e-5f);

    float4 g = ((const float4*)gamma)[lane];
    float4 be = ((const float4*)beta)[lane];
    float4 o;
    o.x = fmaxf(fmaf((acc.x - mu) * rstd, g.x, be.x), 0.f);
    o.y = fmaxf(fmaf((acc.y - mu) * rstd, g.y, be.y), 0.f);
    o.z = fmaxf(fmaf((acc.z - mu) * rstd, g.z, be.z), 0.f);
    o.w = fmaxf(fmaf((acc.w - mu) * rstd, g.w, be.w), 0.f);
    ((float4*)out)[((unsigned)gw << 5) + lane] = o;
}

// ---------------- host side ----------------
static cudaStream_t g_s2 = nullptr;
static cudaEvent_t g_ev_fork = nullptr, g_ev_join = nullptr, g_ev_conv = nullptr;
struct GcnInit {
    GcnInit() {
        cudaStreamCreateWithFlags(&g_s2, cudaStreamNonBlocking);
        cudaEventCreateWithFlags(&g_ev_fork, cudaEventDisableTiming);
        cudaEventCreateWithFlags(&g_ev_join, cudaEventDisableTiming);
        cudaEventCreateWithFlags(&g_ev_conv, cudaEventDisableTiming);
    }
};
static GcnInit g_gcn_init;

extern "C" void kernel_launch(void* const* d_in, const int* in_sizes, int n_in,
                              void* d_out, int out_size) {
    const float* x = nullptr;
    const int* erow = nullptr;
    const int* ecol = nullptr;
    const float* W[3] = {nullptr, nullptr, nullptr};
    const float* vec[9] = {};
    int we = 0, ve = 0, ee = 0, E = 0;

    for (int i = 0; i < n_in; i++) {
        int s = in_sizes[i];
        if (s == out_size && x == nullptr) {
            x = (const float*)d_in[i];
        } else if (s == 16384 && we < 3) {
            W[we++] = (const float*)d_in[i];
        } else if (s == 128 && ve < 9) {
            vec[ve++] = (const float*)d_in[i];
        } else if (ee < 2) {
            if (ee == 0) erow = (const int*)d_in[i];
            else ecol = (const int*)d_in[i];
            E = s;
            ee++;
        }
    }

    int N = out_size / 128;
    int nb = (N + SCB - 1) / SCB;
    __half *pH = nullptr, *pT = nullptr, *pW16 = nullptr;
    int* pDeg = nullptr;
    cudaGetSymbolAddress((void**)&pH, g_H);
    cudaGetSymbolAddress((void**)&pT, g_T);
    cudaGetSymbolAddress((void**)&pW16, g_W16);
    cudaGetSymbolAddress((void**)&pDeg, g_deg);

    cudaFuncSetAttribute((const void*)k_gemm_ps,
                         cudaFuncAttributeMaxDynamicSharedMemorySize, GEMM_SMEM);
    cudaFuncSetAttribute((const void*)k_aggr_gemm,
                         cudaFuncAttributeMaxDynamicSharedMemorySize, FUSED_SMEM);

    int tiles = (N + 63) / 64;
    int pgrid = tiles < 444 ? tiles : 444;   // persistent gemm1 grid
    int aggr_blocks = (N + 7) / 8;

    // ---- fork: preprocessing on s2, concurrent with layer-1 GEMM on stream 0 ----
    cudaEventRecord(g_ev_fork, 0);
    cudaStreamWaitEvent(g_s2, g_ev_fork, 0);

    cudaMemsetAsync(pDeg, 0, (size_t)N * sizeof(int), g_s2);
    k_count<<<(E + 255) / 256, 256, 0, g_s2>>>(erow, E);
    k_blocksum_dinv<<<nb, SCB, 0, g_s2>>>(N);
    k_bscan<<<1, 128, 0, g_s2>>>(nb);
    k_blockscan<<<nb, SCB, 0, g_s2>>>(N);
    k_scatter<<<(E + 255) / 256, 256, 0, g_s2>>>(erow, ecol, E);
    cudaEventRecord(g_ev_join, g_s2);
    k_convW<<<16, 256, 0, g_s2>>>(W[1], W[2]);
    cudaEventRecord(g_ev_conv, g_s2);

    // layer 1 GEMM: x @ W1 -> H (persistent, overlaps CSR build)
    k_gemm_ps<<<pgrid, 256, GEMM_SMEM>>>(x, W[0], pH, N);
    cudaStreamWaitEvent(0, g_ev_join, 0);
    cudaStreamWaitEvent(0, g_ev_conv, 0);

    // layer 2 fused: aggr(H)+LN+ReLU @ W2 -> T
    k_aggr_gemm<<<tiles, 256, FUSED_SMEM>>>(pH, pW16, pT,
                                            vec[0], vec[1], vec[2], N);
    // layer 3 fused: aggr(T)+LN+ReLU @ W3 -> H
    k_aggr_gemm<<<tiles, 256, FUSED_SMEM>>>(pT, pW16 + DD * DD, pH,
                                            vec[3], vec[4], vec[5], N);
    // final aggregate: H -> d_out (fp32)
    k_aggr_f32<<<aggr_blocks, 256>>>(pH, (float*)d_out, vec[6], vec[7], vec[8], N);
}

// round 14
// speedup vs baseline: 1.1568x; 1.1568x over previous
#include <cuda_runtime.h>
#include <cuda_fp16.h>
#include <cstdint>

#define NMAX 100000
#define EMAX 1600000
#define DD 128
#define SCB 1024   // scan tile size

// ---- scratch (device globals: allocation-free rule) ----
__device__ int    g_deg[NMAX];
__device__ float  g_dinv[NMAX];
__device__ int    g_rowptr[NMAX + 1];
__device__ int    g_cursor[NMAX];
__device__ __align__(16) int2 g_colw[EMAX];
__device__ int    g_bsum[(NMAX + SCB - 1) / SCB];
__device__ int    g_boff[(NMAX + SCB - 1) / SCB];
__device__ __half g_H[(size_t)NMAX * DD];
__device__ __half g_T[(size_t)NMAX * DD];
__device__ __align__(16) __half g_W16[2 * DD * DD];

// ---------------- preprocessing (R10 form — frozen) ----------------
__global__ void k_count(const int* __restrict__ row, int E) {
    int i = blockIdx.x * blockDim.x + threadIdx.x;
    if (i < E) atomicAdd(&g_deg[row[i]], 1);
}

__global__ void __launch_bounds__(SCB) k_blocksum_dinv(int n) {
    __shared__ int s[SCB];
    int i = blockIdx.x * SCB + threadIdx.x;
    int d = 0;
    if (i < n) {
        d = g_deg[i];
        g_dinv[i] = rsqrtf((float)(d + 1));  // +1 self loop
    }
    s[threadIdx.x] = d;
    __syncthreads();
#pragma unroll
    for (int off = SCB / 2; off > 0; off >>= 1) {
        if (threadIdx.x < off) s[threadIdx.x] += s[threadIdx.x + off];
        __syncthreads();
    }
    if (threadIdx.x == 0) g_bsum[blockIdx.x] = s[0];
}

__global__ void k_bscan(int nb) {
    __shared__ int s[128];
    int t = threadIdx.x;
    s[t] = (t < nb) ? g_bsum[t] : 0;
    __syncthreads();
#pragma unroll
    for (int off = 1; off < 128; off <<= 1) {
        int v = (t >= off) ? s[t - off] : 0;
        __syncthreads();
        s[t] += v;
        __syncthreads();
    }
    if (t < nb) g_boff[t] = (t == 0) ? 0 : s[t - 1];
}

__global__ void __launch_bounds__(SCB) k_blockscan(int n) {
    __shared__ int s[SCB];
    int i = blockIdx.x * SCB + threadIdx.x;
    int d = (i < n) ? g_deg[i] : 0;
    s[threadIdx.x] = d;
    __syncthreads();
#pragma unroll
    for (int off = 1; off < SCB; off <<= 1) {
        int v = (threadIdx.x >= off) ? s[threadIdx.x - off] : 0;
        __syncthreads();
        s[threadIdx.x] += v;
        __syncthreads();
    }
    int boff = g_boff[blockIdx.x];
    if (i < n) {
        int excl = boff + s[threadIdx.x] - d;
        g_rowptr[i] = excl;
        g_cursor[i] = excl;
        if (i == n - 1) g_rowptr[n] = boff + s[threadIdx.x];
    }
}

__global__ void k_scatter(const int* __restrict__ row, const int* __restrict__ col, int E) {
    int i = blockIdx.x * blockDim.x + threadIdx.x;
    if (i < E) {
        int r = row[i];
        int c = col[i];
        int p = atomicAdd(&g_cursor[r], 1);
        float w = g_dinv[r] * g_dinv[c];
        g_colw[p] = make_int2(c, __float_as_int(w));
    }
}

__global__ void k_convW(const float* __restrict__ Wa, const float* __restrict__ Wb) {
    int i = blockIdx.x * blockDim.x + threadIdx.x;
    if (i < 4096) {
        float4 v = ((const float4*)Wa)[i];
        half2 lo = __floats2half2_rn(v.x, v.y);
        half2 hi = __floats2half2_rn(v.z, v.w);
        uint2 pk;
        pk.x = *(unsigned int*)&lo;
        pk.y = *(unsigned int*)&hi;
        ((uint2*)g_W16)[i] = pk;
        v = ((const float4*)Wb)[i];
        lo = __floats2half2_rn(v.x, v.y);
        hi = __floats2half2_rn(v.z, v.w);
        pk.x = *(unsigned int*)&lo;
        pk.y = *(unsigned int*)&hi;
        ((uint2*)g_W16)[4096 + i] = pk;
    }
}

// ---------------- persistent tensor-core GEMM ----------------
__device__ __forceinline__ void ldsm4(uint32_t (&r)[4], const void* p) {
    uint32_t a = (uint32_t)__cvta_generic_to_shared(p);
    asm volatile("ldmatrix.sync.aligned.m8n8.x4.shared.b16 {%0,%1,%2,%3}, [%4];"
                 : "=r"(r[0]), "=r"(r[1]), "=r"(r[2]), "=r"(r[3]) : "r"(a));
}
__device__ __forceinline__ void ldsm4t(uint32_t (&r)[4], const void* p) {
    uint32_t a = (uint32_t)__cvta_generic_to_shared(p);
    asm volatile("ldmatrix.sync.aligned.m8n8.x4.trans.shared.b16 {%0,%1,%2,%3}, [%4];"
                 : "=r"(r[0]), "=r"(r[1]), "=r"(r[2]), "=r"(r[3]) : "r"(a));
}
__device__ __forceinline__ void mma16816(float (&c)[4], const uint32_t (&a)[4],
                                         uint32_t b0, uint32_t b1) {
    asm volatile(
        "mma.sync.aligned.m16n8k16.row.col.f32.f16.f16.f32 "
        "{%0,%1,%2,%3}, {%4,%5,%6,%7}, {%8,%9}, {%0,%1,%2,%3};"
        : "+f"(c[0]), "+f"(c[1]), "+f"(c[2]), "+f"(c[3])
        : "r"(a[0]), "r"(a[1]), "r"(a[2]), "r"(a[3]), "r"(b0), "r"(b1));
}

#define ASTRIDE 136
#define GEMM_SMEM ((2 * 64 + 128) * ASTRIDE * 2)

template <bool F32IN, bool F32W>
__global__ void __launch_bounds__(256) k_gemm_ps(const void* __restrict__ Xv,
                                                 const void* __restrict__ Wv,
                                                 __half* __restrict__ H, int n) {
    extern __shared__ __half sm[];
    __half* As2 = sm;                       // 2 x [64][ASTRIDE]
    __half* Bs = sm + 2 * 64 * ASTRIDE;     // [128][ASTRIDE]
    int t = threadIdx.x;

    if (F32W) {
        const float4* W4 = (const float4*)Wv;
        for (int i = t; i < 4096; i += 256) {
            int r = i >> 5, c = (i & 31) * 4;
            float4 v = W4[i];
            *(half2*)&Bs[r * ASTRIDE + c]     = __floats2half2_rn(v.x, v.y);
            *(half2*)&Bs[r * ASTRIDE + c + 2] = __floats2half2_rn(v.z, v.w);
        }
    } else {
        const uint2* W2 = (const uint2*)Wv;
        for (int i = t; i < 4096; i += 256) {
            int r = i >> 5, c = (i & 31) * 4;
            *(uint2*)&Bs[r * ASTRIDE + c] = W2[i];
        }
    }

    int lane = t & 31;
    int wid = t >> 5;
    int wm = (wid & 3) * 16;
    int wn = (wid >> 2) * 64;
    int lr = lane & 15;
    int lc = (lane >> 4) * 8;

    int buf = 0;
    for (int row0 = blockIdx.x * 64; row0 < n; row0 += gridDim.x * 64, buf ^= 1) {
        __half* As = As2 + buf * 64 * ASTRIDE;
        if (F32IN) {
            const float4* X4 = (const float4*)Xv;
            for (int i = t; i < 2048; i += 256) {
                int r = i >> 5, c = (i & 31) * 4;
                float4 v = (row0 + r < n) ? X4[(size_t)(row0 + r) * 32 + (i & 31)]
                                          : make_float4(0.f, 0.f, 0.f, 0.f);
                *(half2*)&As[r * ASTRIDE + c]     = __floats2half2_rn(v.x, v.y);
                *(half2*)&As[r * ASTRIDE + c + 2] = __floats2half2_rn(v.z, v.w);
            }
        } else {
            const uint2* X2 = (const uint2*)Xv;
            for (int i = t; i < 2048; i += 256) {
                int r = i >> 5, c = (i & 31) * 4;
                uint2 v = (row0 + r < n) ? X2[(size_t)(row0 + r) * 32 + (i & 31)]
                                         : make_uint2(0u, 0u);
                *(uint2*)&As[r * ASTRIDE + c] = v;
            }
        }
        __syncthreads();

        float acc[8][4];
#pragma unroll
        for (int i = 0; i < 8; i++) { acc[i][0] = 0.f; acc[i][1] = 0.f; acc[i][2] = 0.f; acc[i][3] = 0.f; }

#pragma unroll
        for (int k0 = 0; k0 < 128; k0 += 16) {
            uint32_t a[4];
            ldsm4(a, &As[(wm + lr) * ASTRIDE + k0 + lc]);
#pragma unroll
            for (int p = 0; p < 4; p++) {
                uint32_t b[4];
                ldsm4t(b, &Bs[(k0 + lr) * ASTRIDE + wn + p * 16 + lc]);
                mma16816(acc[2 * p],     a, b[0], b[1]);
                mma16816(acc[2 * p + 1], a, b[2], b[3]);
            }
        }

        int orow = row0 + wm + (lane >> 2);
#pragma unroll
        for (int nt = 0; nt < 8; nt++) {
            int ocol = wn + nt * 8 + (lane & 3) * 2;
            if (orow < n)
                *(half2*)&H[(size_t)orow * 128 + ocol] = __floats2half2_rn(acc[nt][0], acc[nt][1]);
            if (orow + 8 < n)
                *(half2*)&H[(size_t)(orow + 8) * 128 + ocol] = __floats2half2_rn(acc[nt][2], acc[nt][3]);
        }
    }
}

// ---------------- fused aggregate + bias + LayerNorm + ReLU ----------------
// one warp per node; lane handles 4 features; __ldcg gathers (L1 bypass).
template <typename OUT>
__global__ void __launch_bounds__(256) k_aggr(const __half* __restrict__ H,
                                              OUT* __restrict__ out,
                                              const float* __restrict__ bias,
                                              const float* __restrict__ gamma,
                                              const float* __restrict__ beta,
                                              int n) {
    int gw = (blockIdx.x * blockDim.x + threadIdx.x) >> 5;
    unsigned lane = threadIdx.x & 31;
    if (gw >= n) return;

    const uint2* H2 = (const uint2*)H;
    float di = g_dinv[gw];
    float ws = di * di;

    uint2 hp = __ldcg(&H2[((unsigned)gw << 5) + lane]);
    float2 h01 = __half22float2(*(half2*)&hp.x);
    float2 h23 = __half22float2(*(half2*)&hp.y);
    float4 acc;
    acc.x = ws * h01.x; acc.y = ws * h01.y; acc.z = ws * h23.x; acc.w = ws * h23.y;

    int s = g_rowptr[gw];
    int e = g_rowptr[gw + 1];
    int j = s;

#define EDGE_FMA_V(V, WB)                                                      \
    do {                                                                       \
        float w_ = __int_as_float(WB);                                         \
        float2 a_ = __half22float2(*(half2*)&(V).x);                           \
        float2 b_ = __half22float2(*(half2*)&(V).y);                           \
        acc.x = fmaf(w_, a_.x, acc.x);                                         \
        acc.y = fmaf(w_, a_.y, acc.y);                                         \
        acc.z = fmaf(w_, b_.x, acc.z);                                         \
        acc.w = fmaf(w_, b_.y, acc.w);                                         \
    } while (0)

    if (j < e && (j & 1)) {
        int2 cw = __ldg(&g_colw[j]);
        uint2 v = __ldcg(&H2[((unsigned)cw.x << 5) + lane]);
        EDGE_FMA_V(v, cw.y);
        j++;
    }
    for (; j + 7 < e; j += 8) {
        int4 q0 = __ldg((const int4*)&g_colw[j]);
        int4 q1 = __ldg((const int4*)&g_colw[j + 2]);
        int4 q2 = __ldg((const int4*)&g_colw[j + 4]);
        int4 q3 = __ldg((const int4*)&g_colw[j + 6]);
        uint2 v0 = __ldcg(&H2[((unsigned)q0.x << 5) + lane]);
        uint2 v1 = __ldcg(&H2[((unsigned)q0.z << 5) + lane]);
        uint2 v2 = __ldcg(&H2[((unsigned)q1.x << 5) + lane]);
        uint2 v3 = __ldcg(&H2[((unsigned)q1.z << 5) + lane]);
        uint2 v4 = __ldcg(&H2[((unsigned)q2.x << 5) + lane]);
        uint2 v5 = __ldcg(&H2[((unsigned)q2.z << 5) + lane]);
        uint2 v6 = __ldcg(&H2[((unsigned)q3.x << 5) + lane]);
        uint2 v7 = __ldcg(&H2[((unsigned)q3.z << 5) + lane]);
        EDGE_FMA_V(v0, q0.y);
        EDGE_FMA_V(v1, q0.w);
        EDGE_FMA_V(v2, q1.y);
        EDGE_FMA_V(v3, q1.w);
        EDGE_FMA_V(v4, q2.y);
        EDGE_FMA_V(v5, q2.w);
        EDGE_FMA_V(v6, q3.y);
        EDGE_FMA_V(v7, q3.w);
    }
    for (; j + 1 < e; j += 2) {
        int4 q = __ldg((const int4*)&g_colw[j]);
        uint2 v0 = __ldcg(&H2[((unsigned)q.x << 5) + lane]);
        uint2 v1 = __ldcg(&H2[((unsigned)q.z << 5) + lane]);
        EDGE_FMA_V(v0, q.y);
        EDGE_FMA_V(v1, q.w);
    }
    if (j < e) {
        int2 cw = __ldg(&g_colw[j]);
        uint2 v = __ldcg(&H2[((unsigned)cw.x << 5) + lane]);
        EDGE_FMA_V(v, cw.y);
    }
#undef EDGE_FMA_V

    float4 b = ((const float4*)bias)[lane];
    acc.x += b.x; acc.y += b.y; acc.z += b.z; acc.w += b.w;

    float sum = acc.x + acc.y + acc.z + acc.w;
    float sq = acc.x * acc.x + acc.y * acc.y + acc.z * acc.z + acc.w * acc.w;
#pragma unroll
    for (int o = 16; o > 0; o >>= 1) {
        sum += __shfl_xor_sync(0xffffffffu, sum, o);
        sq  += __shfl_xor_sync(0xffffffffu, sq, o);
    }
    float mu = sum * (1.0f / 128.0f);
    float var = sq * (1.0f / 128.0f) - mu * mu;
    float rstd = rsqrtf(var + 1e-5f);

    float4 g = ((const float4*)gamma)[lane];
    float4 be = ((const float4*)beta)[lane];
    float ox = fmaxf(fmaf((acc.x - mu) * rstd, g.x, be.x), 0.f);
    float oy = fmaxf(fmaf((acc.y - mu) * rstd, g.y, be.y), 0.f);
    float oz = fmaxf(fmaf((acc.z - mu) * rstd, g.z, be.z), 0.f);
    float ow = fmaxf(fmaf((acc.w - mu) * rstd, g.w, be.w), 0.f);

    if constexpr (sizeof(OUT) == 2) {
        uint2 pk;
        half2 lo = __floats2half2_rn(ox, oy);
        half2 hi = __floats2half2_rn(oz, ow);
        pk.x = *(unsigned int*)&lo;
        pk.y = *(unsigned int*)&hi;
        ((uint2*)out)[((unsigned)gw << 5) + lane] = pk;
    } else {
        ((float4*)out)[((unsigned)gw << 5) + lane] = make_float4(ox, oy, oz, ow);
    }
}

// ---------------- host side ----------------
static cudaStream_t g_s2 = nullptr;
static cudaEvent_t g_ev_fork = nullptr, g_ev_join = nullptr, g_ev_conv = nullptr;
struct GcnInit {
    GcnInit() {
        cudaStreamCreateWithFlags(&g_s2, cudaStreamNonBlocking);
        cudaEventCreateWithFlags(&g_ev_fork, cudaEventDisableTiming);
        cudaEventCreateWithFlags(&g_ev_join, cudaEventDisableTiming);
        cudaEventCreateWithFlags(&g_ev_conv, cudaEventDisableTiming);
    }
};
static GcnInit g_gcn_init;

extern "C" void kernel_launch(void* const* d_in, const int* in_sizes, int n_in,
                              void* d_out, int out_size) {
    const float* x = nullptr;
    const int* erow = nullptr;
    const int* ecol = nullptr;
    const float* W[3] = {nullptr, nullptr, nullptr};
    const float* vec[9] = {};
    int we = 0, ve = 0, ee = 0, E = 0;

    for (int i = 0; i < n_in; i++) {
        int s = in_sizes[i];
        if (s == out_size && x == nullptr) {
            x = (const float*)d_in[i];
        } else if (s == 16384 && we < 3) {
            W[we++] = (const float*)d_in[i];
        } else if (s == 128 && ve < 9) {
            vec[ve++] = (const float*)d_in[i];
        } else if (ee < 2) {
            if (ee == 0) erow = (const int*)d_in[i];
            else ecol = (const int*)d_in[i];
            E = s;
            ee++;
        }
    }

    int N = out_size / 128;
    int nb = (N + SCB - 1) / SCB;
    __half *pH = nullptr, *pT = nullptr, *pW16 = nullptr;
    int* pDeg = nullptr;
    cudaGetSymbolAddress((void**)&pH, g_H);
    cudaGetSymbolAddress((void**)&pT, g_T);
    cudaGetSymbolAddress((void**)&pW16, g_W16);
    cudaGetSymbolAddress((void**)&pDeg, g_deg);

    cudaFuncSetAttribute((const void*)k_gemm_ps<true, true>,
                         cudaFuncAttributeMaxDynamicSharedMemorySize, GEMM_SMEM);
    cudaFuncSetAttribute((const void*)k_gemm_ps<false, false>,
                         cudaFuncAttributeMaxDynamicSharedMemorySize, GEMM_SMEM);

    int tiles = (N + 63) / 64;
    int pgrid = tiles < 444 ? tiles : 444;   // 3 blocks/SM x 148 SMs
    int aggr_blocks = (N + 7) / 8;

    // ---- fork: preprocessing on s2, concurrent with layer-1 GEMM on stream 0 ----
    cudaEventRecord(g_ev_fork, 0);
    cudaStreamWaitEvent(g_s2, g_ev_fork, 0);

    // convW first: independent, gets W16 ready long before gemm2
    k_convW<<<16, 256, 0, g_s2>>>(W[1], W[2]);
    cudaEventRecord(g_ev_conv, g_s2);
    cudaMemsetAsync(pDeg, 0, (size_t)N * sizeof(int), g_s2);
    k_count<<<(E + 255) / 256, 256, 0, g_s2>>>(erow, E);
    k_blocksum_dinv<<<nb, SCB, 0, g_s2>>>(N);
    k_bscan<<<1, 128, 0, g_s2>>>(nb);
    k_blockscan<<<nb, SCB, 0, g_s2>>>(N);
    k_scatter<<<(E + 255) / 256, 256, 0, g_s2>>>(erow, ecol, E);
    cudaEventRecord(g_ev_join, g_s2);

    // layer 1 GEMM (fp32 inputs + fp32 W), overlaps CSR build
    k_gemm_ps<true, true><<<pgrid, 256, GEMM_SMEM>>>(x, W[0], pH, N);
    cudaStreamWaitEvent(0, g_ev_join, 0);

    // layer 1 aggregate
    k_aggr<__half><<<aggr_blocks, 256>>>(pH, pT, vec[0], vec[1], vec[2], N);
    // layer 2
    cudaStreamWaitEvent(0, g_ev_conv, 0);
    k_gemm_ps<false, false><<<pgrid, 256, GEMM_SMEM>>>(pT, pW16, pH, N);
    k_aggr<__half><<<aggr_blocks, 256>>>(pH, pT, vec[3], vec[4], vec[5], N);
    // layer 3
    k_gemm_ps<false, false><<<pgrid, 256, GEMM_SMEM>>>(pT, pW16 + DD * DD, pH, N);
    k_aggr<float><<<aggr_blocks, 256>>>(pH, (float*)d_out, vec[6], vec[7], vec[8], N);
}